// round 5
// baseline (speedup 1.0000x reference)
#include <cuda_runtime.h>
#include <cstdint>

#define BDIM 4
#define SDIM 2048
#define HDIM 1024
#define NH   16
#define DH   64

#define MB 256
#define NB 128
#define KB 16

// Scratch (device globals: no allocation allowed in kernel_launch)
__device__ float g_Q[(size_t)BDIM * NH * SDIM * DH];
__device__ float g_K[(size_t)BDIM * NH * SDIM * DH];
__device__ float g_V[(size_t)BDIM * NH * SDIM * DH];
__device__ float g_ctx[(size_t)BDIM * SDIM * HDIM];

// ---------------------------------------------------------------------------
__device__ __forceinline__ float to_tf32(float x) {
    float r;
    asm("cvt.rna.tf32.f32 %0, %1;" : "=f"(r) : "f"(x));
    return r;
}
__device__ __forceinline__ float4 tf32x4(float4 v) {
    return make_float4(to_tf32(v.x), to_tf32(v.y), to_tf32(v.z), to_tf32(v.w));
}
__device__ __forceinline__ void mma_tf32(float* c, const unsigned* a,
                                         const unsigned* b) {
    asm volatile(
        "mma.sync.aligned.m16n8k8.row.col.f32.tf32.tf32.f32 "
        "{%0,%1,%2,%3}, {%4,%5,%6,%7}, {%8,%9}, {%0,%1,%2,%3};\n"
        : "+f"(c[0]), "+f"(c[1]), "+f"(c[2]), "+f"(c[3])
        : "r"(a[0]), "r"(a[1]), "r"(a[2]), "r"(a[3]), "r"(b[0]), "r"(b[1]));
}

// ---------------------------------------------------------------------------
// Dense GEMM: C[M,N] = A[M,K] @ B[N,K]^T + bias, tf32 MMA, double-buffered.
// MODE 0: direct row-major C. MODE 1: scatter to [B,H,S,Dh].
// Block tile 256x128, BK=16, 256 threads, 8 warps (4m x 2n), warp tile 64x64.
// ---------------------------------------------------------------------------
template <int MODE>
__global__ void __launch_bounds__(256, 1) gemm64(
    const float* __restrict__ A, const float* __restrict__ Bm,
    const float* __restrict__ bias, float* __restrict__ C,
    int K, int ldc, float alpha)
{
    extern __shared__ char smem_raw[];
    float (*As)[MB][20] = (float(*)[MB][20])smem_raw;
    float (*Bs)[NB][20] = (float(*)[NB][20])(smem_raw + 2 * MB * 20 * 4);

    const int tid  = threadIdx.x;
    const int wid  = tid >> 5, lane = tid & 31;
    const int wm   = wid >> 1, wn = wid & 1;
    const int g    = lane >> 2, qd = lane & 3;
    const int brow = blockIdx.y * MB;
    const int bcol = blockIdx.x * NB;

    const int lr = tid >> 2;        // 0..63
    const int lc = (tid & 3) * 4;   // 0,4,8,12

    float acc[4][8][4];
#pragma unroll
    for (int i = 0; i < 4; i++)
#pragma unroll
        for (int j = 0; j < 8; j++)
#pragma unroll
            for (int r = 0; r < 4; r++) acc[i][j][r] = 0.f;

    float4 pa[4], pb[2];
#pragma unroll
    for (int p = 0; p < 4; p++)
        pa[p] = *(const float4*)(A + (size_t)(brow + lr + 64 * p) * K + lc);
#pragma unroll
    for (int p = 0; p < 2; p++)
        pb[p] = *(const float4*)(Bm + (size_t)(bcol + lr + 64 * p) * K + lc);
#pragma unroll
    for (int p = 0; p < 4; p++) *(float4*)&As[0][lr + 64 * p][lc] = tf32x4(pa[p]);
#pragma unroll
    for (int p = 0; p < 2; p++) *(float4*)&Bs[0][lr + 64 * p][lc] = tf32x4(pb[p]);
    __syncthreads();

    int buf = 0;
    for (int k0 = 0; k0 < K; k0 += KB, buf ^= 1) {
        const bool more = (k0 + KB) < K;
        if (more) {
#pragma unroll
            for (int p = 0; p < 4; p++)
                pa[p] = *(const float4*)(A + (size_t)(brow + lr + 64 * p) * K + k0 + KB + lc);
#pragma unroll
            for (int p = 0; p < 2; p++)
                pb[p] = *(const float4*)(Bm + (size_t)(bcol + lr + 64 * p) * K + k0 + KB + lc);
        }

#pragma unroll
        for (int ks = 0; ks < 2; ks++) {
            const int kb = ks * 8;
            unsigned a[4][4], b[8][2];
#pragma unroll
            for (int mt = 0; mt < 4; mt++) {
                const int r0 = wm * 64 + mt * 16 + g;
                a[mt][0] = __float_as_uint(As[buf][r0    ][kb + qd]);
                a[mt][1] = __float_as_uint(As[buf][r0 + 8][kb + qd]);
                a[mt][2] = __float_as_uint(As[buf][r0    ][kb + qd + 4]);
                a[mt][3] = __float_as_uint(As[buf][r0 + 8][kb + qd + 4]);
            }
#pragma unroll
            for (int nt = 0; nt < 8; nt++) {
                const int c0 = wn * 64 + nt * 8 + g;
                b[nt][0] = __float_as_uint(Bs[buf][c0][kb + qd]);
                b[nt][1] = __float_as_uint(Bs[buf][c0][kb + qd + 4]);
            }
#pragma unroll
            for (int mt = 0; mt < 4; mt++)
#pragma unroll
                for (int nt = 0; nt < 8; nt++)
                    mma_tf32(acc[mt][nt], a[mt], b[nt]);
        }

        if (more) {
#pragma unroll
            for (int p = 0; p < 4; p++) *(float4*)&As[buf ^ 1][lr + 64 * p][lc] = tf32x4(pa[p]);
#pragma unroll
            for (int p = 0; p < 2; p++) *(float4*)&Bs[buf ^ 1][lr + 64 * p][lc] = tf32x4(pb[p]);
            __syncthreads();
        }
    }

#pragma unroll
    for (int mt = 0; mt < 4; mt++) {
#pragma unroll
        for (int nt = 0; nt < 8; nt++) {
            const int cc = bcol + wn * 64 + nt * 8 + 2 * qd;
            const float bx = bias[cc], by = bias[cc + 1];
#pragma unroll
            for (int half = 0; half < 2; half++) {
                const int r = brow + wm * 64 + mt * 16 + g + half * 8;
                float2 v;
                v.x = alpha * acc[mt][nt][2 * half]     + bx;
                v.y = alpha * acc[mt][nt][2 * half + 1] + by;
                if (MODE == 1) {
                    const int b_ = r / SDIM, s = r % SDIM;
                    const int h  = cc / DH,  d = cc % DH;
                    *(float2*)&C[(((size_t)(b_ * NH + h)) * SDIM + s) * DH + d] = v;
                } else {
                    *(float2*)&C[(size_t)r * ldc + cc] = v;
                }
            }
        }
    }
}

// ---------------------------------------------------------------------------
// Scores: per (b,h)  E[2048,2048] = Q @ K^T / 8.   K-dim = 64 → ONE smem
// load, one sync, straight MMA. Block tile 256x128, 8 warps 64x64.
// ---------------------------------------------------------------------------
__global__ void __launch_bounds__(256, 1) scores_k64(
    const float* __restrict__ Qg, const float* __restrict__ Kg,
    float* __restrict__ att)
{
    extern __shared__ char smem_raw[];
    float (*As)[68] = (float(*)[68])smem_raw;                       // 256 x 64
    float (*Bs)[68] = (float(*)[68])(smem_raw + 256 * 68 * 4);      // 128 x 64

    const int bh = blockIdx.z;
    const float* A = Qg + (size_t)bh * SDIM * DH;
    const float* B = Kg + (size_t)bh * SDIM * DH;
    float* C = att + (size_t)bh * SDIM * SDIM;

    const int tid  = threadIdx.x;
    const int wid  = tid >> 5, lane = tid & 31;
    const int wm   = wid >> 1, wn = wid & 1;
    const int g    = lane >> 2, qd = lane & 3;
    const int brow = blockIdx.y * 256;
    const int bcol = blockIdx.x * 128;

    // Load A tile 256x64 (16 float4/thread), B tile 128x64 (8 float4/thread)
#pragma unroll
    for (int i = 0; i < 16; i++) {
        const int idx = tid + i * 256;
        const int r = idx >> 4, c = (idx & 15) * 4;
        float4 x = *(const float4*)(A + (size_t)(brow + r) * DH + c);
        *(float4*)&As[r][c] = tf32x4(x);
    }
#pragma unroll
    for (int i = 0; i < 8; i++) {
        const int idx = tid + i * 256;
        const int r = idx >> 4, c = (idx & 15) * 4;
        float4 x = *(const float4*)(B + (size_t)(bcol + r) * DH + c);
        *(float4*)&Bs[r][c] = tf32x4(x);
    }
    __syncthreads();

    float acc[4][8][4];
#pragma unroll
    for (int i = 0; i < 4; i++)
#pragma unroll
        for (int j = 0; j < 8; j++)
#pragma unroll
            for (int r = 0; r < 4; r++) acc[i][j][r] = 0.f;

#pragma unroll
    for (int ks = 0; ks < 8; ks++) {
        const int kb = ks * 8;
        unsigned a[4][4], b[8][2];
#pragma unroll
        for (int mt = 0; mt < 4; mt++) {
            const int r0 = wm * 64 + mt * 16 + g;
            a[mt][0] = __float_as_uint(As[r0    ][kb + qd]);
            a[mt][1] = __float_as_uint(As[r0 + 8][kb + qd]);
            a[mt][2] = __float_as_uint(As[r0    ][kb + qd + 4]);
            a[mt][3] = __float_as_uint(As[r0 + 8][kb + qd + 4]);
        }
#pragma unroll
        for (int nt = 0; nt < 8; nt++) {
            const int c0 = wn * 64 + nt * 8 + g;
            b[nt][0] = __float_as_uint(Bs[c0][kb + qd]);
            b[nt][1] = __float_as_uint(Bs[c0][kb + qd + 4]);
        }
#pragma unroll
        for (int mt = 0; mt < 4; mt++)
#pragma unroll
            for (int nt = 0; nt < 8; nt++)
                mma_tf32(acc[mt][nt], a[mt], b[nt]);
    }

#pragma unroll
    for (int mt = 0; mt < 4; mt++) {
#pragma unroll
        for (int nt = 0; nt < 8; nt++) {
            const int cc = bcol + wn * 64 + nt * 8 + 2 * qd;
#pragma unroll
            for (int half = 0; half < 2; half++) {
                const int r = brow + wm * 64 + mt * 16 + g + half * 8;
                float2 v;
                v.x = 0.125f * acc[mt][nt][2 * half];
                v.y = 0.125f * acc[mt][nt][2 * half + 1];
                *(float2*)&C[(size_t)r * SDIM + cc] = v;
            }
        }
    }
}

// ---------------------------------------------------------------------------
// Fused masked softmax + PV.  CTA = 128 query rows of one (b,h).
// Pass 1: per-row max & sum (warp per row). Pass 2: per 128-col chunk:
// normalize+write probs (att output), stage P,V tf32 in smem, MMA into ctx.
// ---------------------------------------------------------------------------
__global__ void __launch_bounds__(256, 1) softmax_pv(
    float* __restrict__ att, const int* __restrict__ mask,
    float* __restrict__ ctx)
{
    extern __shared__ char smem_raw[];
    float (*Ps)[132] = (float(*)[132])smem_raw;                         // 128x128
    float (*Vs)[72]  = (float(*)[72])(smem_raw + 128 * 132 * 4);        // 128x64
    int*   Ms  = (int*)(smem_raw + 128 * 132 * 4 + 128 * 72 * 4);       // 2048
    float* Rm  = (float*)(Ms + SDIM);                                   // 128
    float* Ri  = Rm + 128;                                              // 128

    const int bh = blockIdx.y;
    const int q0 = blockIdx.x * 128;
    const int b_ = bh / NH, h = bh % NH;
    const int tid = threadIdx.x, wid = tid >> 5, lane = tid & 31;
    const int g = lane >> 2, qd = lane & 3;

    float* Ag = att + ((size_t)bh * SDIM + q0) * SDIM;
    const float* Vg = g_V + (size_t)bh * SDIM * DH;

    for (int i = tid; i < SDIM / 4; i += 256)
        ((int4*)Ms)[i] = ((const int4*)(mask + b_ * SDIM))[i];
    __syncthreads();

    // ---- Pass 1: row max & sum (warp per row, 16 rows/warp) ----
    for (int rr = 0; rr < 16; rr++) {
        const int r = wid * 16 + rr;
        const float4* rp4 = (const float4*)(Ag + (size_t)r * SDIM);
        float4 vbuf[16];
        float m = -3.4e38f;
#pragma unroll
        for (int j = 0; j < 16; j++) {
            float4 x = rp4[lane + j * 32];
            int4 mm = ((const int4*)Ms)[lane + j * 32];
            if (mm.x == 0) x.x = -1e10f;
            if (mm.y == 0) x.y = -1e10f;
            if (mm.z == 0) x.z = -1e10f;
            if (mm.w == 0) x.w = -1e10f;
            vbuf[j] = x;
            m = fmaxf(m, fmaxf(fmaxf(x.x, x.y), fmaxf(x.z, x.w)));
        }
#pragma unroll
        for (int o = 16; o > 0; o >>= 1) m = fmaxf(m, __shfl_xor_sync(0xffffffffu, m, o));
        float s = 0.f;
#pragma unroll
        for (int j = 0; j < 16; j++) {
            s += __expf(vbuf[j].x - m) + __expf(vbuf[j].y - m)
               + __expf(vbuf[j].z - m) + __expf(vbuf[j].w - m);
        }
#pragma unroll
        for (int o = 16; o > 0; o >>= 1) s += __shfl_xor_sync(0xffffffffu, s, o);
        if (lane == 0) { Rm[r] = m; Ri[r] = 1.f / s; }
    }
    __syncthreads();

    // ---- Pass 2: chunked normalize + write probs + MMA with V ----
    float acc[8][4];
#pragma unroll
    for (int j = 0; j < 8; j++)
#pragma unroll
        for (int r = 0; r < 4; r++) acc[j][r] = 0.f;

    for (int kt = 0; kt < 16; kt++) {
        const int kbase = kt * 128;
        // V chunk 128x64 -> Vs (8 float4/thread)
#pragma unroll
        for (int i = 0; i < 8; i++) {
            const int idx = tid + i * 256;
            const int vr = idx >> 4, vc = (idx & 15) * 4;
            float4 x = *(const float4*)(Vg + (size_t)(kbase + vr) * DH + vc);
            *(float4*)&Vs[vr][vc] = tf32x4(x);
        }
        // P chunk 128x128: read energies, normalize, write probs, stage smem
#pragma unroll
        for (int i = 0; i < 16; i++) {
            const int idx = tid + i * 256;
            const int pr = idx >> 5, pc = (idx & 31) * 4;
            float* ep = Ag + (size_t)pr * SDIM + kbase + pc;
            float4 x = *(const float4*)ep;
            const int c = kbase + pc;
            if (Ms[c + 0] == 0) x.x = -1e10f;
            if (Ms[c + 1] == 0) x.y = -1e10f;
            if (Ms[c + 2] == 0) x.z = -1e10f;
            if (Ms[c + 3] == 0) x.w = -1e10f;
            const float m = Rm[pr], inv = Ri[pr];
            float4 p;
            p.x = __expf(x.x - m) * inv;
            p.y = __expf(x.y - m) * inv;
            p.z = __expf(x.z - m) * inv;
            p.w = __expf(x.w - m) * inv;
            *(float4*)ep = p;
            *(float4*)&Ps[pr][pc] = tf32x4(p);
        }
        __syncthreads();

        // MMA: warp handles rows 16*wid..16*wid+15, all 64 cols, k=128
#pragma unroll
        for (int ks = 0; ks < 16; ks++) {
            const int kb = ks * 8;
            unsigned a[4], b[8][2];
            const int r0 = wid * 16 + g;
            a[0] = __float_as_uint(Ps[r0    ][kb + qd]);
            a[1] = __float_as_uint(Ps[r0 + 8][kb + qd]);
            a[2] = __float_as_uint(Ps[r0    ][kb + qd + 4]);
            a[3] = __float_as_uint(Ps[r0 + 8][kb + qd + 4]);
#pragma unroll
            for (int nt = 0; nt < 8; nt++) {
                const int c0 = nt * 8 + g;
                b[nt][0] = __float_as_uint(Vs[kb + qd    ][c0]);
                b[nt][1] = __float_as_uint(Vs[kb + qd + 4][c0]);
            }
#pragma unroll
            for (int nt = 0; nt < 8; nt++)
                mma_tf32(acc[nt], a, b[nt]);
        }
        __syncthreads();
    }

    // ---- Epilogue: ctx[b, q0+row, h*64+d] ----
#pragma unroll
    for (int nt = 0; nt < 8; nt++) {
        const int d = nt * 8 + 2 * qd;
#pragma unroll
        for (int half = 0; half < 2; half++) {
            const int row = wid * 16 + g + half * 8;
            float2 v;
            v.x = acc[nt][2 * half];
            v.y = acc[nt][2 * half + 1];
            *(float2*)&ctx[((size_t)(b_ * SDIM + q0 + row)) * HDIM + h * DH + d] = v;
        }
    }
}

// ---------------------------------------------------------------------------
extern "C" void kernel_launch(void* const* d_in, const int* in_sizes, int n_in,
                              void* d_out, int out_size)
{
    const float* query  = (const float*)d_in[0];
    const float* key_in = (const float*)d_in[1];
    const float* value  = (const float*)d_in[2];
    const int*   mask   = (const int*)  d_in[3];
    const float* Wq = (const float*)d_in[4],  *bq = (const float*)d_in[5];
    const float* Wk = (const float*)d_in[6],  *bk = (const float*)d_in[7];
    const float* Wv = (const float*)d_in[8],  *bv = (const float*)d_in[9];
    const float* Wo = (const float*)d_in[10], *bo = (const float*)d_in[11];
    float* out = (float*)d_out;

    float *qbuf, *kbuf, *vbuf, *cbuf;
    cudaGetSymbolAddress((void**)&qbuf, g_Q);
    cudaGetSymbolAddress((void**)&kbuf, g_K);
    cudaGetSymbolAddress((void**)&vbuf, g_V);
    cudaGetSymbolAddress((void**)&cbuf, g_ctx);

    const long long XE = (long long)BDIM * SDIM * HDIM;       // 8,388,608
    float* att = out + XE;                                    // [B,H,S,S]

    const int smem_g  = 2 * (MB + NB) * 20 * 4;               // 61,440
    const int smem_s  = (256 + 128) * 68 * 4;                 // 104,448
    const int smem_pv = 128 * 132 * 4 + 128 * 72 * 4 + SDIM * 4 + 256 * 4; // 113,664
    cudaFuncSetAttribute(gemm64<0>, cudaFuncAttributeMaxDynamicSharedMemorySize, smem_g);
    cudaFuncSetAttribute(gemm64<1>, cudaFuncAttributeMaxDynamicSharedMemorySize, smem_g);
    cudaFuncSetAttribute(scores_k64, cudaFuncAttributeMaxDynamicSharedMemorySize, smem_s);
    cudaFuncSetAttribute(softmax_pv, cudaFuncAttributeMaxDynamicSharedMemorySize, smem_pv);

    // 1) QKV projections, scatter to [B,H,S,Dh]
    const dim3 gp(HDIM / NB, (BDIM * SDIM) / MB, 1);
    gemm64<1><<<gp, 256, smem_g>>>(query,  Wq, bq, qbuf, HDIM, HDIM, 1.f);
    gemm64<1><<<gp, 256, smem_g>>>(key_in, Wk, bk, kbuf, HDIM, HDIM, 1.f);
    gemm64<1><<<gp, 256, smem_g>>>(value,  Wv, bv, vbuf, HDIM, HDIM, 1.f);

    // 2) Scores -> energies in att region
    scores_k64<<<dim3(SDIM / 128, SDIM / 256, BDIM * NH), 256, smem_s>>>(qbuf, kbuf, att);

    // 3) Fused softmax (writes att probs) + PV (writes ctx)
    softmax_pv<<<dim3(SDIM / 128, BDIM * NH), 256, smem_pv>>>(att, mask, cbuf);

    // 4) Output projection -> x
    gemm64<0><<<gp, 256, smem_g>>>(cbuf, Wo, bo, out, HDIM, HDIM, 1.f);
}

// round 8
// speedup vs baseline: 1.3875x; 1.3875x over previous
#include <cuda_runtime.h>
#include <cstdint>

#define BDIM 4
#define SDIM 2048
#define HDIM 1024
#define NH   16
#define DH   64

#define MB 256
#define NB 128
#define KB 16
#define PMB 256

// Scratch (device globals: no allocation allowed in kernel_launch)
__device__ float g_Q[(size_t)BDIM * NH * SDIM * DH];
__device__ float g_K[(size_t)BDIM * NH * SDIM * DH];
__device__ float g_V[(size_t)BDIM * NH * SDIM * DH];
__device__ float g_ctx[(size_t)BDIM * SDIM * HDIM];

// ---------------------------------------------------------------------------
__device__ __forceinline__ float to_tf32(float x) {
    float r;
    asm("cvt.rna.tf32.f32 %0, %1;" : "=f"(r) : "f"(x));
    return r;
}
__device__ __forceinline__ float4 tf32x4(float4 v) {
    return make_float4(to_tf32(v.x), to_tf32(v.y), to_tf32(v.z), to_tf32(v.w));
}
__device__ __forceinline__ void mma_tf32(float* c, const unsigned* a,
                                         const unsigned* b) {
    asm volatile(
        "mma.sync.aligned.m16n8k8.row.col.f32.tf32.tf32.f32 "
        "{%0,%1,%2,%3}, {%4,%5,%6,%7}, {%8,%9}, {%0,%1,%2,%3};\n"
        : "+f"(c[0]), "+f"(c[1]), "+f"(c[2]), "+f"(c[3])
        : "r"(a[0]), "r"(a[1]), "r"(a[2]), "r"(a[3]), "r"(b[0]), "r"(b[1]));
}

// ---------------------------------------------------------------------------
// Dense GEMM: C[M,N] = A[M,K] @ B[N,K]^T + bias, tf32 MMA, double-buffered.
// MODE 0: direct row-major C. MODE 1: scatter to [B,H,S,Dh].
// Block tile 256x128, BK=16, 256 threads, 8 warps (4m x 2n), warp tile 64x64.
// ---------------------------------------------------------------------------
template <int MODE>
__global__ void __launch_bounds__(256, 1) gemm64(
    const float* __restrict__ A, const float* __restrict__ Bm,
    const float* __restrict__ bias, float* __restrict__ C,
    int K, int ldc, float alpha)
{
    extern __shared__ char smem_raw[];
    float (*As)[MB][20] = (float(*)[MB][20])smem_raw;
    float (*Bs)[NB][20] = (float(*)[NB][20])(smem_raw + 2 * MB * 20 * 4);

    const int tid  = threadIdx.x;
    const int wid  = tid >> 5, lane = tid & 31;
    const int wm   = wid >> 1, wn = wid & 1;
    const int g    = lane >> 2, qd = lane & 3;
    const int brow = blockIdx.y * MB;
    const int bcol = blockIdx.x * NB;

    const int lr = tid >> 2;        // 0..63
    const int lc = (tid & 3) * 4;   // 0,4,8,12

    float acc[4][8][4];
#pragma unroll
    for (int i = 0; i < 4; i++)
#pragma unroll
        for (int j = 0; j < 8; j++)
#pragma unroll
            for (int r = 0; r < 4; r++) acc[i][j][r] = 0.f;

    float4 pa[4], pb[2];
#pragma unroll
    for (int p = 0; p < 4; p++)
        pa[p] = *(const float4*)(A + (size_t)(brow + lr + 64 * p) * K + lc);
#pragma unroll
    for (int p = 0; p < 2; p++)
        pb[p] = *(const float4*)(Bm + (size_t)(bcol + lr + 64 * p) * K + lc);
#pragma unroll
    for (int p = 0; p < 4; p++) *(float4*)&As[0][lr + 64 * p][lc] = tf32x4(pa[p]);
#pragma unroll
    for (int p = 0; p < 2; p++) *(float4*)&Bs[0][lr + 64 * p][lc] = tf32x4(pb[p]);
    __syncthreads();

    int buf = 0;
    for (int k0 = 0; k0 < K; k0 += KB, buf ^= 1) {
        const bool more = (k0 + KB) < K;
        if (more) {
#pragma unroll
            for (int p = 0; p < 4; p++)
                pa[p] = *(const float4*)(A + (size_t)(brow + lr + 64 * p) * K + k0 + KB + lc);
#pragma unroll
            for (int p = 0; p < 2; p++)
                pb[p] = *(const float4*)(Bm + (size_t)(bcol + lr + 64 * p) * K + k0 + KB + lc);
        }

#pragma unroll
        for (int ks = 0; ks < 2; ks++) {
            const int kb = ks * 8;
            unsigned a[4][4], b[8][2];
#pragma unroll
            for (int mt = 0; mt < 4; mt++) {
                const int r0 = wm * 64 + mt * 16 + g;
                a[mt][0] = __float_as_uint(As[buf][r0    ][kb + qd]);
                a[mt][1] = __float_as_uint(As[buf][r0 + 8][kb + qd]);
                a[mt][2] = __float_as_uint(As[buf][r0    ][kb + qd + 4]);
                a[mt][3] = __float_as_uint(As[buf][r0 + 8][kb + qd + 4]);
            }
#pragma unroll
            for (int nt = 0; nt < 8; nt++) {
                const int c0 = wn * 64 + nt * 8 + g;
                b[nt][0] = __float_as_uint(Bs[buf][c0][kb + qd]);
                b[nt][1] = __float_as_uint(Bs[buf][c0][kb + qd + 4]);
            }
#pragma unroll
            for (int mt = 0; mt < 4; mt++)
#pragma unroll
                for (int nt = 0; nt < 8; nt++)
                    mma_tf32(acc[mt][nt], a[mt], b[nt]);
        }

        if (more) {
#pragma unroll
            for (int p = 0; p < 4; p++) *(float4*)&As[buf ^ 1][lr + 64 * p][lc] = tf32x4(pa[p]);
#pragma unroll
            for (int p = 0; p < 2; p++) *(float4*)&Bs[buf ^ 1][lr + 64 * p][lc] = tf32x4(pb[p]);
            __syncthreads();
        }
    }

#pragma unroll
    for (int mt = 0; mt < 4; mt++) {
#pragma unroll
        for (int nt = 0; nt < 8; nt++) {
            const int cc = bcol + wn * 64 + nt * 8 + 2 * qd;
            const float bx = bias[cc], by = bias[cc + 1];
#pragma unroll
            for (int half = 0; half < 2; half++) {
                const int r = brow + wm * 64 + mt * 16 + g + half * 8;
                float2 v;
                v.x = alpha * acc[mt][nt][2 * half]     + bx;
                v.y = alpha * acc[mt][nt][2 * half + 1] + by;
                if (MODE == 1) {
                    const int b_ = r / SDIM, s = r % SDIM;
                    const int h  = cc / DH,  d = cc % DH;
                    *(float2*)&C[(((size_t)(b_ * NH + h)) * SDIM + s) * DH + d] = v;
                } else {
                    *(float2*)&C[(size_t)r * ldc + cc] = v;
                }
            }
        }
    }
}

// ---------------------------------------------------------------------------
// Scores: per (b,h)  E[2048,2048] = Q @ K^T / 8.  K-dim = 64 → one smem load,
// one sync, straight MMA. Block tile 128x128 (smem 70KB → 2 CTAs/SM).
// 8 warps (4m x 2n), warp tile 32x64.
// ---------------------------------------------------------------------------
__global__ void __launch_bounds__(256, 2) scores_k64(
    const float* __restrict__ Qg, const float* __restrict__ Kg,
    float* __restrict__ att)
{
    extern __shared__ char smem_raw[];
    float (*As)[68] = (float(*)[68])smem_raw;                       // 128 x 64
    float (*Bs)[68] = (float(*)[68])(smem_raw + 128 * 68 * 4);      // 128 x 64

    const int bh = blockIdx.z;
    const float* A = Qg + (size_t)bh * SDIM * DH;
    const float* B = Kg + (size_t)bh * SDIM * DH;
    float* C = att + (size_t)bh * SDIM * SDIM;

    const int tid  = threadIdx.x;
    const int wid  = tid >> 5, lane = tid & 31;
    const int wm   = wid >> 1, wn = wid & 1;
    const int g    = lane >> 2, qd = lane & 3;
    const int brow = blockIdx.y * 128;
    const int bcol = blockIdx.x * 128;

    // Load A/B tiles 128x64 (8 float4/thread each)
#pragma unroll
    for (int i = 0; i < 8; i++) {
        const int idx = tid + i * 256;
        const int r = idx >> 4, c = (idx & 15) * 4;
        float4 x = *(const float4*)(A + (size_t)(brow + r) * DH + c);
        *(float4*)&As[r][c] = tf32x4(x);
        float4 y = *(const float4*)(B + (size_t)(bcol + r) * DH + c);
        *(float4*)&Bs[r][c] = tf32x4(y);
    }
    __syncthreads();

    float acc[2][8][4];
#pragma unroll
    for (int i = 0; i < 2; i++)
#pragma unroll
        for (int j = 0; j < 8; j++)
#pragma unroll
            for (int r = 0; r < 4; r++) acc[i][j][r] = 0.f;

#pragma unroll
    for (int ks = 0; ks < 8; ks++) {
        const int kb = ks * 8;
        unsigned a[2][4], b[8][2];
#pragma unroll
        for (int mt = 0; mt < 2; mt++) {
            const int r0 = wm * 32 + mt * 16 + g;
            a[mt][0] = __float_as_uint(As[r0    ][kb + qd]);
            a[mt][1] = __float_as_uint(As[r0 + 8][kb + qd]);
            a[mt][2] = __float_as_uint(As[r0    ][kb + qd + 4]);
            a[mt][3] = __float_as_uint(As[r0 + 8][kb + qd + 4]);
        }
#pragma unroll
        for (int nt = 0; nt < 8; nt++) {
            const int c0 = wn * 64 + nt * 8 + g;
            b[nt][0] = __float_as_uint(Bs[c0][kb + qd]);
            b[nt][1] = __float_as_uint(Bs[c0][kb + qd + 4]);
        }
#pragma unroll
        for (int mt = 0; mt < 2; mt++)
#pragma unroll
            for (int nt = 0; nt < 8; nt++)
                mma_tf32(acc[mt][nt], a[mt], b[nt]);
    }

#pragma unroll
    for (int mt = 0; mt < 2; mt++) {
#pragma unroll
        for (int nt = 0; nt < 8; nt++) {
            const int cc = bcol + wn * 64 + nt * 8 + 2 * qd;
#pragma unroll
            for (int half = 0; half < 2; half++) {
                const int r = brow + wm * 32 + mt * 16 + g + half * 8;
                float2 v;
                v.x = 0.125f * acc[mt][nt][2 * half];
                v.y = 0.125f * acc[mt][nt][2 * half + 1];
                *(float2*)&C[(size_t)r * SDIM + cc] = v;
            }
        }
    }
}

// ---------------------------------------------------------------------------
// In-place masked softmax over last dim of att [B*H*S, S]; warp per row.
// ---------------------------------------------------------------------------
__global__ void __launch_bounds__(256) softmax_rows(
    float* __restrict__ att, const int* __restrict__ mask)
{
    const int wid  = threadIdx.x >> 5;
    const int lane = threadIdx.x & 31;
    const long long row = (long long)blockIdx.x * 8 + wid;

    float* rp = att + (size_t)row * SDIM;
    const int b_ = (int)(row / ((long long)NH * SDIM));
    const int4* mrow = (const int4*)(mask + b_ * SDIM);
    const float4* rp4 = (const float4*)rp;

    float v[64];
    float m = -3.4e38f;
#pragma unroll
    for (int j = 0; j < 16; j++) {
        float4 x = rp4[lane + j * 32];
        int4 mm  = mrow[lane + j * 32];
        if (mm.x == 0) x.x = -1e10f;
        if (mm.y == 0) x.y = -1e10f;
        if (mm.z == 0) x.z = -1e10f;
        if (mm.w == 0) x.w = -1e10f;
        v[4 * j + 0] = x.x; v[4 * j + 1] = x.y;
        v[4 * j + 2] = x.z; v[4 * j + 3] = x.w;
        m = fmaxf(m, fmaxf(fmaxf(x.x, x.y), fmaxf(x.z, x.w)));
    }
#pragma unroll
    for (int o = 16; o > 0; o >>= 1) m = fmaxf(m, __shfl_xor_sync(0xffffffffu, m, o));

    float s = 0.f;
#pragma unroll
    for (int i = 0; i < 64; i++) {
        v[i] = __expf(v[i] - m);
        s += v[i];
    }
#pragma unroll
    for (int o = 16; o > 0; o >>= 1) s += __shfl_xor_sync(0xffffffffu, s, o);
    const float inv = 1.f / s;

    float4* wp4 = (float4*)rp;
#pragma unroll
    for (int j = 0; j < 16; j++) {
        float4 x;
        x.x = v[4 * j + 0] * inv; x.y = v[4 * j + 1] * inv;
        x.z = v[4 * j + 2] * inv; x.w = v[4 * j + 3] * inv;
        wp4[lane + j * 32] = x;
    }
}

// ---------------------------------------------------------------------------
// PV: per (b,h): ctx_part[2048,64] = P[2048,2048] @ V[2048,64]
// Block tile 256x64, BK=16, 256 threads, 8 m-stacked warps, warp tile 32x64.
// Small smem (25KB) + modest regs → 2 CTAs/SM.
// ---------------------------------------------------------------------------
__global__ void __launch_bounds__(256, 2) gemm_pv64(
    const float* __restrict__ P, float* __restrict__ ctx)
{
    __shared__ float As[PMB][20];
    __shared__ float Vs[16][72];

    const int bh = blockIdx.y;
    const float* A  = P + (size_t)bh * SDIM * SDIM;
    const float* Vg = g_V + (size_t)bh * SDIM * DH;

    const int tid  = threadIdx.x;
    const int wid  = tid >> 5, lane = tid & 31;
    const int g    = lane >> 2, qd = lane & 3;
    const int brow = blockIdx.x * PMB;

    const int lr = tid >> 2;        // 0..63
    const int lc = (tid & 3) * 4;
    const int vr = tid >> 4;        // 0..15
    const int vc = (tid & 15) * 4;  // 0..60

    float acc[2][8][4];
#pragma unroll
    for (int i = 0; i < 2; i++)
#pragma unroll
        for (int j = 0; j < 8; j++)
#pragma unroll
            for (int r = 0; r < 4; r++) acc[i][j][r] = 0.f;

    float4 pa[4], pv;
#pragma unroll
    for (int p = 0; p < 4; p++)
        pa[p] = *(const float4*)(A + (size_t)(brow + lr + 64 * p) * SDIM + lc);
    pv = *(const float4*)(Vg + (size_t)vr * DH + vc);

    for (int k0 = 0; k0 < SDIM; k0 += KB) {
#pragma unroll
        for (int p = 0; p < 4; p++)
            *(float4*)&As[lr + 64 * p][lc] = tf32x4(pa[p]);
        *(float4*)&Vs[vr][vc] = tf32x4(pv);
        __syncthreads();

        if (k0 + KB < SDIM) {
#pragma unroll
            for (int p = 0; p < 4; p++)
                pa[p] = *(const float4*)(A + (size_t)(brow + lr + 64 * p) * SDIM + k0 + KB + lc);
            pv = *(const float4*)(Vg + (size_t)(k0 + KB + vr) * DH + vc);
        }

#pragma unroll
        for (int ks = 0; ks < 2; ks++) {
            const int kb = ks * 8;
            unsigned a[2][4], b[8][2];
#pragma unroll
            for (int mt = 0; mt < 2; mt++) {
                const int r0 = wid * 32 + mt * 16 + g;
                a[mt][0] = __float_as_uint(As[r0    ][kb + qd]);
                a[mt][1] = __float_as_uint(As[r0 + 8][kb + qd]);
                a[mt][2] = __float_as_uint(As[r0    ][kb + qd + 4]);
                a[mt][3] = __float_as_uint(As[r0 + 8][kb + qd + 4]);
            }
#pragma unroll
            for (int nt = 0; nt < 8; nt++) {
                const int c0 = nt * 8 + g;
                b[nt][0] = __float_as_uint(Vs[kb + qd    ][c0]);
                b[nt][1] = __float_as_uint(Vs[kb + qd + 4][c0]);
            }
#pragma unroll
            for (int mt = 0; mt < 2; mt++)
#pragma unroll
                for (int nt = 0; nt < 8; nt++)
                    mma_tf32(acc[mt][nt], a[mt], b[nt]);
        }
        __syncthreads();
    }

    const int b_ = bh / NH, h = bh % NH;
#pragma unroll
    for (int mt = 0; mt < 2; mt++) {
#pragma unroll
        for (int nt = 0; nt < 8; nt++) {
            const int d = nt * 8 + 2 * qd;
#pragma unroll
            for (int half = 0; half < 2; half++) {
                const int s = brow + wid * 32 + mt * 16 + g + half * 8;
                float2 v;
                v.x = acc[mt][nt][2 * half];
                v.y = acc[mt][nt][2 * half + 1];
                *(float2*)&ctx[((size_t)(b_ * SDIM + s)) * HDIM + h * DH + d] = v;
            }
        }
    }
}

// ---------------------------------------------------------------------------
extern "C" void kernel_launch(void* const* d_in, const int* in_sizes, int n_in,
                              void* d_out, int out_size)
{
    const float* query  = (const float*)d_in[0];
    const float* key_in = (const float*)d_in[1];
    const float* value  = (const float*)d_in[2];
    const int*   mask   = (const int*)  d_in[3];
    const float* Wq = (const float*)d_in[4],  *bq = (const float*)d_in[5];
    const float* Wk = (const float*)d_in[6],  *bk = (const float*)d_in[7];
    const float* Wv = (const float*)d_in[8],  *bv = (const float*)d_in[9];
    const float* Wo = (const float*)d_in[10], *bo = (const float*)d_in[11];
    float* out = (float*)d_out;

    float *qbuf, *kbuf, *vbuf, *cbuf;
    cudaGetSymbolAddress((void**)&qbuf, g_Q);
    cudaGetSymbolAddress((void**)&kbuf, g_K);
    cudaGetSymbolAddress((void**)&vbuf, g_V);
    cudaGetSymbolAddress((void**)&cbuf, g_ctx);

    const long long XE = (long long)BDIM * SDIM * HDIM;       // 8,388,608
    float* att = out + XE;                                    // [B,H,S,S]

    const int smem_g = 2 * (MB + NB) * 20 * 4;                // 61,440
    const int smem_s = 2 * 128 * 68 * 4;                      // 69,632
    cudaFuncSetAttribute(gemm64<0>, cudaFuncAttributeMaxDynamicSharedMemorySize, smem_g);
    cudaFuncSetAttribute(gemm64<1>, cudaFuncAttributeMaxDynamicSharedMemorySize, smem_g);
    cudaFuncSetAttribute(scores_k64, cudaFuncAttributeMaxDynamicSharedMemorySize, smem_s);

    // 1) QKV projections, scatter to [B,H,S,Dh]
    const dim3 gp(HDIM / NB, (BDIM * SDIM) / MB, 1);
    gemm64<1><<<gp, 256, smem_g>>>(query,  Wq, bq, qbuf, HDIM, HDIM, 1.f);
    gemm64<1><<<gp, 256, smem_g>>>(key_in, Wk, bk, kbuf, HDIM, HDIM, 1.f);
    gemm64<1><<<gp, 256, smem_g>>>(value,  Wv, bv, vbuf, HDIM, HDIM, 1.f);

    // 2) Scores -> energies in att region
    scores_k64<<<dim3(SDIM / 128, SDIM / 128, BDIM * NH), 256, smem_s>>>(qbuf, kbuf, att);

    // 3) Softmax (mask + normalize) in place -> attention probs (2nd output)
    softmax_rows<<<(BDIM * NH * SDIM) / 8, 256>>>(att, mask);

    // 4) PV: ctx = P @ V
    gemm_pv64<<<dim3(SDIM / PMB, BDIM * NH), 256>>>(att, cbuf);

    // 5) Output projection -> x
    gemm64<0><<<gp, 256, smem_g>>>(cbuf, Wo, bo, out, HDIM, HDIM, 1.f);
}

// round 10
// speedup vs baseline: 1.4311x; 1.0315x over previous
#include <cuda_runtime.h>
#include <cstdint>

#define BDIM 4
#define SDIM 2048
#define HDIM 1024
#define NH   16
#define DH   64

#define MB 256
#define NB 128
#define KB 16

// Scratch (device globals: no allocation allowed in kernel_launch)
__device__ float g_Q[(size_t)BDIM * NH * SDIM * DH];
__device__ float g_K[(size_t)BDIM * NH * SDIM * DH];
__device__ float g_V[(size_t)BDIM * NH * SDIM * DH];
__device__ float g_ctx[(size_t)BDIM * SDIM * HDIM];
__device__ float2 g_stats[(size_t)BDIM * NH * SDIM];   // (row_max, 1/row_sum)

// ---------------------------------------------------------------------------
__device__ __forceinline__ float to_tf32(float x) {
    float r;
    asm("cvt.rna.tf32.f32 %0, %1;" : "=f"(r) : "f"(x));
    return r;
}
__device__ __forceinline__ float4 tf32x4(float4 v) {
    return make_float4(to_tf32(v.x), to_tf32(v.y), to_tf32(v.z), to_tf32(v.w));
}
__device__ __forceinline__ void mma_tf32(float* c, const unsigned* a,
                                         const unsigned* b) {
    asm volatile(
        "mma.sync.aligned.m16n8k8.row.col.f32.tf32.tf32.f32 "
        "{%0,%1,%2,%3}, {%4,%5,%6,%7}, {%8,%9}, {%0,%1,%2,%3};\n"
        : "+f"(c[0]), "+f"(c[1]), "+f"(c[2]), "+f"(c[3])
        : "r"(a[0]), "r"(a[1]), "r"(a[2]), "r"(a[3]), "r"(b[0]), "r"(b[1]));
}

// ---------------------------------------------------------------------------
// Dense GEMM: C[M,N] = A[M,K] @ B[N,K]^T + bias, tf32 MMA, double-buffered.
// MODE 0: direct row-major C. MODE 1: scatter to [B,H,S,Dh].
// Block tile 256x128, BK=16, 256 threads, 8 warps (4m x 2n), warp tile 64x64.
// ---------------------------------------------------------------------------
template <int MODE>
__global__ void __launch_bounds__(256, 1) gemm64(
    const float* __restrict__ A, const float* __restrict__ Bm,
    const float* __restrict__ bias, float* __restrict__ C,
    int K, int ldc, float alpha)
{
    extern __shared__ char smem_raw[];
    float (*As)[MB][20] = (float(*)[MB][20])smem_raw;
    float (*Bs)[NB][20] = (float(*)[NB][20])(smem_raw + 2 * MB * 20 * 4);

    const int tid  = threadIdx.x;
    const int wid  = tid >> 5, lane = tid & 31;
    const int wm   = wid >> 1, wn = wid & 1;
    const int g    = lane >> 2, qd = lane & 3;
    const int brow = blockIdx.y * MB;
    const int bcol = blockIdx.x * NB;

    const int lr = tid >> 2;
    const int lc = (tid & 3) * 4;

    float acc[4][8][4];
#pragma unroll
    for (int i = 0; i < 4; i++)
#pragma unroll
        for (int j = 0; j < 8; j++)
#pragma unroll
            for (int r = 0; r < 4; r++) acc[i][j][r] = 0.f;

    float4 pa[4], pb[2];
#pragma unroll
    for (int p = 0; p < 4; p++)
        pa[p] = *(const float4*)(A + (size_t)(brow + lr + 64 * p) * K + lc);
#pragma unroll
    for (int p = 0; p < 2; p++)
        pb[p] = *(const float4*)(Bm + (size_t)(bcol + lr + 64 * p) * K + lc);
#pragma unroll
    for (int p = 0; p < 4; p++) *(float4*)&As[0][lr + 64 * p][lc] = tf32x4(pa[p]);
#pragma unroll
    for (int p = 0; p < 2; p++) *(float4*)&Bs[0][lr + 64 * p][lc] = tf32x4(pb[p]);
    __syncthreads();

    int buf = 0;
    for (int k0 = 0; k0 < K; k0 += KB, buf ^= 1) {
        const bool more = (k0 + KB) < K;
        if (more) {
#pragma unroll
            for (int p = 0; p < 4; p++)
                pa[p] = *(const float4*)(A + (size_t)(brow + lr + 64 * p) * K + k0 + KB + lc);
#pragma unroll
            for (int p = 0; p < 2; p++)
                pb[p] = *(const float4*)(Bm + (size_t)(bcol + lr + 64 * p) * K + k0 + KB + lc);
        }

#pragma unroll
        for (int ks = 0; ks < 2; ks++) {
            const int kb = ks * 8;
            unsigned a[4][4], b[8][2];
#pragma unroll
            for (int mt = 0; mt < 4; mt++) {
                const int r0 = wm * 64 + mt * 16 + g;
                a[mt][0] = __float_as_uint(As[buf][r0    ][kb + qd]);
                a[mt][1] = __float_as_uint(As[buf][r0 + 8][kb + qd]);
                a[mt][2] = __float_as_uint(As[buf][r0    ][kb + qd + 4]);
                a[mt][3] = __float_as_uint(As[buf][r0 + 8][kb + qd + 4]);
            }
#pragma unroll
            for (int nt = 0; nt < 8; nt++) {
                const int c0 = wn * 64 + nt * 8 + g;
                b[nt][0] = __float_as_uint(Bs[buf][c0][kb + qd]);
                b[nt][1] = __float_as_uint(Bs[buf][c0][kb + qd + 4]);
            }
#pragma unroll
            for (int mt = 0; mt < 4; mt++)
#pragma unroll
                for (int nt = 0; nt < 8; nt++)
                    mma_tf32(acc[mt][nt], a[mt], b[nt]);
        }

        if (more) {
#pragma unroll
            for (int p = 0; p < 4; p++) *(float4*)&As[buf ^ 1][lr + 64 * p][lc] = tf32x4(pa[p]);
#pragma unroll
            for (int p = 0; p < 2; p++) *(float4*)&Bs[buf ^ 1][lr + 64 * p][lc] = tf32x4(pb[p]);
            __syncthreads();
        }
    }

#pragma unroll
    for (int mt = 0; mt < 4; mt++) {
#pragma unroll
        for (int nt = 0; nt < 8; nt++) {
            const int cc = bcol + wn * 64 + nt * 8 + 2 * qd;
            const float bx = bias[cc], by = bias[cc + 1];
#pragma unroll
            for (int half = 0; half < 2; half++) {
                const int r = brow + wm * 64 + mt * 16 + g + half * 8;
                float2 v;
                v.x = alpha * acc[mt][nt][2 * half]     + bx;
                v.y = alpha * acc[mt][nt][2 * half + 1] + by;
                if (MODE == 1) {
                    const int b_ = r / SDIM, s = r % SDIM;
                    const int h  = cc / DH,  d = cc % DH;
                    *(float2*)&C[(((size_t)(b_ * NH + h)) * SDIM + s) * DH + d] = v;
                } else {
                    *(float2*)&C[(size_t)r * ldc + cc] = v;
                }
            }
        }
    }
}

// ---------------------------------------------------------------------------
// Flash attention: per (b,h, 128 q-rows): stream K/V in 128-key chunks,
// online softmax, accumulate P@V in registers. Writes ctx + row stats ONLY.
// 8 warps m-stacked, warp tile 16 rows x full chunk width.
// ---------------------------------------------------------------------------
__global__ void __launch_bounds__(256, 1) flash_attn(
    const int* __restrict__ mask, float* __restrict__ ctx,
    float2* __restrict__ stats)
{
    extern __shared__ char smem_raw[];
    float (*Qs)[68]  = (float(*)[68])smem_raw;                          // 128x64
    float (*Ks)[68]  = (float(*)[68])(smem_raw + 128 * 68 * 4);         // 128x64
    float (*Vs)[72]  = (float(*)[72])(smem_raw + 2 * 128 * 68 * 4);     // 128x64 [k][d]
    float (*Ps)[132] = (float(*)[132])(smem_raw + 2 * 128 * 68 * 4 + 128 * 72 * 4);
    int*   Ms        = (int*)(smem_raw + 2 * 128 * 68 * 4 + 128 * 72 * 4 + 128 * 132 * 4);

    const int bh = blockIdx.y;
    const int q0 = blockIdx.x * 128;
    const int b_ = bh / NH, h = bh % NH;
    const int tid = threadIdx.x, wid = tid >> 5, lane = tid & 31;
    const int g = lane >> 2, qd = lane & 3;
    const int r0 = wid * 16 + g;

    const float* Qg = g_Q + ((size_t)bh * SDIM + q0) * DH;
    const float* Kg = g_K + (size_t)bh * SDIM * DH;
    const float* Vg = g_V + (size_t)bh * SDIM * DH;

    // Load Q tile + mask row
#pragma unroll
    for (int i = 0; i < 8; i++) {
        const int idx = tid + i * 256;
        const int r = idx >> 4, c = (idx & 15) * 4;
        *(float4*)&Qs[r][c] = tf32x4(*(const float4*)(Qg + (size_t)r * DH + c));
    }
    for (int i = tid; i < SDIM / 4; i += 256)
        ((int4*)Ms)[i] = ((const int4*)(mask + b_ * SDIM))[i];

    float m_lo = -1e30f, m_hi = -1e30f, s_lo = 0.f, s_hi = 0.f;
    float acc_o[8][4];
#pragma unroll
    for (int j = 0; j < 8; j++)
#pragma unroll
        for (int r = 0; r < 4; r++) acc_o[j][r] = 0.f;

    for (int kt = 0; kt < SDIM / 128; kt++) {
        const int kb0 = kt * 128;
        __syncthreads();   // prev chunk consumed (and Q/mask ready on iter 0)
#pragma unroll
        for (int i = 0; i < 8; i++) {
            const int idx = tid + i * 256;
            const int r = idx >> 4, c = (idx & 15) * 4;
            *(float4*)&Ks[r][c] = tf32x4(*(const float4*)(Kg + (size_t)(kb0 + r) * DH + c));
            *(float4*)&Vs[r][c] = tf32x4(*(const float4*)(Vg + (size_t)(kb0 + r) * DH + c));
        }
        __syncthreads();

        // ---- scores: 16 x 128 per warp ----
        float sacc[16][4];
#pragma unroll
        for (int j = 0; j < 16; j++)
#pragma unroll
            for (int r = 0; r < 4; r++) sacc[j][r] = 0.f;

#pragma unroll
        for (int ks = 0; ks < 8; ks++) {
            const int kb = ks * 8;
            unsigned a[4], b[16][2];
            a[0] = __float_as_uint(Qs[r0    ][kb + qd]);
            a[1] = __float_as_uint(Qs[r0 + 8][kb + qd]);
            a[2] = __float_as_uint(Qs[r0    ][kb + qd + 4]);
            a[3] = __float_as_uint(Qs[r0 + 8][kb + qd + 4]);
#pragma unroll
            for (int nt = 0; nt < 16; nt++) {
                const int c0 = nt * 8 + g;
                b[nt][0] = __float_as_uint(Ks[c0][kb + qd]);
                b[nt][1] = __float_as_uint(Ks[c0][kb + qd + 4]);
            }
#pragma unroll
            for (int nt = 0; nt < 16; nt++)
                mma_tf32(sacc[nt], a, b[nt]);
        }

        // ---- mask + scale + chunk max ----
        float cm_lo = -1e30f, cm_hi = -1e30f;
#pragma unroll
        for (int nt = 0; nt < 16; nt++) {
            const int c0 = kb0 + nt * 8 + 2 * qd;
            const bool z0 = (Ms[c0] == 0), z1 = (Ms[c0 + 1] == 0);
            float s0 = z0 ? -1e10f : sacc[nt][0] * 0.125f;
            float s1 = z1 ? -1e10f : sacc[nt][1] * 0.125f;
            float s2 = z0 ? -1e10f : sacc[nt][2] * 0.125f;
            float s3 = z1 ? -1e10f : sacc[nt][3] * 0.125f;
            sacc[nt][0] = s0; sacc[nt][1] = s1;
            sacc[nt][2] = s2; sacc[nt][3] = s3;
            cm_lo = fmaxf(cm_lo, fmaxf(s0, s1));
            cm_hi = fmaxf(cm_hi, fmaxf(s2, s3));
        }
#pragma unroll
        for (int o = 1; o <= 2; o <<= 1) {
            cm_lo = fmaxf(cm_lo, __shfl_xor_sync(0xffffffffu, cm_lo, o));
            cm_hi = fmaxf(cm_hi, __shfl_xor_sync(0xffffffffu, cm_hi, o));
        }

        const float mn_lo = fmaxf(m_lo, cm_lo), mn_hi = fmaxf(m_hi, cm_hi);
        const float rl = __expf(m_lo - mn_lo), rh = __expf(m_hi - mn_hi);

        // ---- exp, partial sums, stage P to smem (tf32) ----
        float ps_lo = 0.f, ps_hi = 0.f;
#pragma unroll
        for (int nt = 0; nt < 16; nt++) {
            const int c = nt * 8 + 2 * qd;
            const float p0 = __expf(sacc[nt][0] - mn_lo);
            const float p1 = __expf(sacc[nt][1] - mn_lo);
            const float p2 = __expf(sacc[nt][2] - mn_hi);
            const float p3 = __expf(sacc[nt][3] - mn_hi);
            ps_lo += p0 + p1; ps_hi += p2 + p3;
            *(float2*)&Ps[r0    ][c] = make_float2(to_tf32(p0), to_tf32(p1));
            *(float2*)&Ps[r0 + 8][c] = make_float2(to_tf32(p2), to_tf32(p3));
        }
#pragma unroll
        for (int o = 1; o <= 2; o <<= 1) {
            ps_lo += __shfl_xor_sync(0xffffffffu, ps_lo, o);
            ps_hi += __shfl_xor_sync(0xffffffffu, ps_hi, o);
        }
        s_lo = s_lo * rl + ps_lo;
        s_hi = s_hi * rh + ps_hi;
        m_lo = mn_lo; m_hi = mn_hi;

        // rescale O accumulators
#pragma unroll
        for (int nt = 0; nt < 8; nt++) {
            acc_o[nt][0] *= rl; acc_o[nt][1] *= rl;
            acc_o[nt][2] *= rh; acc_o[nt][3] *= rh;
        }
        __syncwarp();

        // ---- PV: O += P(16x128) @ V(128x64) ----
#pragma unroll
        for (int ks = 0; ks < 16; ks++) {
            const int kb = ks * 8;
            unsigned a[4], b[8][2];
            a[0] = __float_as_uint(Ps[r0    ][kb + qd]);
            a[1] = __float_as_uint(Ps[r0 + 8][kb + qd]);
            a[2] = __float_as_uint(Ps[r0    ][kb + qd + 4]);
            a[3] = __float_as_uint(Ps[r0 + 8][kb + qd + 4]);
#pragma unroll
            for (int nt = 0; nt < 8; nt++) {
                const int c0 = nt * 8 + g;
                b[nt][0] = __float_as_uint(Vs[kb + qd    ][c0]);
                b[nt][1] = __float_as_uint(Vs[kb + qd + 4][c0]);
            }
#pragma unroll
            for (int nt = 0; nt < 8; nt++)
                mma_tf32(acc_o[nt], a, b[nt]);
        }
    }

    // ---- epilogue: normalize, write ctx + stats ----
    const float inv_lo = 1.f / s_lo, inv_hi = 1.f / s_hi;
#pragma unroll
    for (int nt = 0; nt < 8; nt++) {
        const int d = h * DH + nt * 8 + 2 * qd;
        float2 v0, v1;
        v0.x = acc_o[nt][0] * inv_lo; v0.y = acc_o[nt][1] * inv_lo;
        v1.x = acc_o[nt][2] * inv_hi; v1.y = acc_o[nt][3] * inv_hi;
        *(float2*)&ctx[((size_t)(b_ * SDIM + q0 + r0    )) * HDIM + d] = v0;
        *(float2*)&ctx[((size_t)(b_ * SDIM + q0 + r0 + 8)) * HDIM + d] = v1;
    }
    if (qd == 0) {
        stats[(size_t)bh * SDIM + q0 + r0    ] = make_float2(m_lo, inv_lo);
        stats[(size_t)bh * SDIM + q0 + r0 + 8] = make_float2(m_hi, inv_hi);
    }
}

// ---------------------------------------------------------------------------
// Probs replay: recompute E tile (bitwise-identical MMA), apply mask, then
// p = exp(s - m) * inv using flash stats; write probs (the 2nd output).
// Block tile 128x128, 2 CTAs/SM. 8 warps (4m x 2n), warp tile 32x64.
// ---------------------------------------------------------------------------
__global__ void __launch_bounds__(256, 2) probs_k64(
    const float* __restrict__ Qg, const float* __restrict__ Kg,
    float* __restrict__ att, const int* __restrict__ mask,
    const float2* __restrict__ stats)
{
    extern __shared__ char smem_raw[];
    float (*As)[68] = (float(*)[68])smem_raw;                       // 128 x 64
    float (*Bs)[68] = (float(*)[68])(smem_raw + 128 * 68 * 4);      // 128 x 64
    float* Sm = (float*)(smem_raw + 2 * 128 * 68 * 4);              // 128 row max
    float* Si = Sm + 128;                                           // 128 row inv
    int*   Mc = (int*)(Si + 128);                                   // 128 col mask

    const int bh = blockIdx.z;
    const float* A = Qg + (size_t)bh * SDIM * DH;
    const float* B = Kg + (size_t)bh * SDIM * DH;
    float* C = att + (size_t)bh * SDIM * SDIM;

    const int tid  = threadIdx.x;
    const int wid  = tid >> 5, lane = tid & 31;
    const int wm   = wid >> 1, wn = wid & 1;
    const int g    = lane >> 2, qd = lane & 3;
    const int brow = blockIdx.y * 128;
    const int bcol = blockIdx.x * 128;
    const int b_   = bh / NH;

#pragma unroll
    for (int i = 0; i < 8; i++) {
        const int idx = tid + i * 256;
        const int r = idx >> 4, c = (idx & 15) * 4;
        *(float4*)&As[r][c] = tf32x4(*(const float4*)(A + (size_t)(brow + r) * DH + c));
        *(float4*)&Bs[r][c] = tf32x4(*(const float4*)(B + (size_t)(bcol + r) * DH + c));
    }
    if (tid < 128) {
        const float2 st = stats[(size_t)bh * SDIM + brow + tid];
        Sm[tid] = st.x; Si[tid] = st.y;
    } else {
        Mc[tid - 128] = mask[b_ * SDIM + bcol + tid - 128];
    }
    __syncthreads();

    float acc[2][8][4];
#pragma unroll
    for (int i = 0; i < 2; i++)
#pragma unroll
        for (int j = 0; j < 8; j++)
#pragma unroll
            for (int r = 0; r < 4; r++) acc[i][j][r] = 0.f;

#pragma unroll
    for (int ks = 0; ks < 8; ks++) {
        const int kb = ks * 8;
        unsigned a[2][4], b[8][2];
#pragma unroll
        for (int mt = 0; mt < 2; mt++) {
            const int r0 = wm * 32 + mt * 16 + g;
            a[mt][0] = __float_as_uint(As[r0    ][kb + qd]);
            a[mt][1] = __float_as_uint(As[r0 + 8][kb + qd]);
            a[mt][2] = __float_as_uint(As[r0    ][kb + qd + 4]);
            a[mt][3] = __float_as_uint(As[r0 + 8][kb + qd + 4]);
        }
#pragma unroll
        for (int nt = 0; nt < 8; nt++) {
            const int c0 = wn * 64 + nt * 8 + g;
            b[nt][0] = __float_as_uint(Bs[c0][kb + qd]);
            b[nt][1] = __float_as_uint(Bs[c0][kb + qd + 4]);
        }
#pragma unroll
        for (int mt = 0; mt < 2; mt++)
#pragma unroll
            for (int nt = 0; nt < 8; nt++)
                mma_tf32(acc[mt][nt], a[mt], b[nt]);
    }

#pragma unroll
    for (int mt = 0; mt < 2; mt++) {
#pragma unroll
        for (int nt = 0; nt < 8; nt++) {
            const int lcc = wn * 64 + nt * 8 + 2 * qd;
            const bool z0 = (Mc[lcc] == 0), z1 = (Mc[lcc + 1] == 0);
#pragma unroll
            for (int half = 0; half < 2; half++) {
                const int lr = wm * 32 + mt * 16 + g + half * 8;
                const float m = Sm[lr], inv = Si[lr];
                float s0 = z0 ? -1e10f : acc[mt][nt][2 * half]     * 0.125f;
                float s1 = z1 ? -1e10f : acc[mt][nt][2 * half + 1] * 0.125f;
                float2 v;
                v.x = __expf(s0 - m) * inv;
                v.y = __expf(s1 - m) * inv;
                *(float2*)&C[(size_t)(brow + lr) * SDIM + bcol + lcc] = v;
            }
        }
    }
}

// ---------------------------------------------------------------------------
extern "C" void kernel_launch(void* const* d_in, const int* in_sizes, int n_in,
                              void* d_out, int out_size)
{
    const float* query  = (const float*)d_in[0];
    const float* key_in = (const float*)d_in[1];
    const float* value  = (const float*)d_in[2];
    const int*   mask   = (const int*)  d_in[3];
    const float* Wq = (const float*)d_in[4],  *bq = (const float*)d_in[5];
    const float* Wk = (const float*)d_in[6],  *bk = (const float*)d_in[7];
    const float* Wv = (const float*)d_in[8],  *bv = (const float*)d_in[9];
    const float* Wo = (const float*)d_in[10], *bo = (const float*)d_in[11];
    float* out = (float*)d_out;

    float *qbuf, *kbuf, *cbuf;
    float2* sbuf;
    cudaGetSymbolAddress((void**)&qbuf, g_Q);
    cudaGetSymbolAddress((void**)&kbuf, g_K);
    cudaGetSymbolAddress((void**)&cbuf, g_ctx);
    cudaGetSymbolAddress((void**)&sbuf, g_stats);
    float* vbuf;
    cudaGetSymbolAddress((void**)&vbuf, g_V);

    const long long XE = (long long)BDIM * SDIM * HDIM;       // 8,388,608
    float* att = out + XE;                                    // [B,H,S,S]

    const int smem_g = 2 * (MB + NB) * 20 * 4;                          // 61,440
    const int smem_f = 2 * 128 * 68 * 4 + 128 * 72 * 4 + 128 * 132 * 4
                     + SDIM * 4;                                        // 180,224
    const int smem_p = 2 * 128 * 68 * 4 + 2 * 128 * 4 + 128 * 4;        // 71,168
    cudaFuncSetAttribute(gemm64<0>, cudaFuncAttributeMaxDynamicSharedMemorySize, smem_g);
    cudaFuncSetAttribute(gemm64<1>, cudaFuncAttributeMaxDynamicSharedMemorySize, smem_g);
    cudaFuncSetAttribute(flash_attn, cudaFuncAttributeMaxDynamicSharedMemorySize, smem_f);
    cudaFuncSetAttribute(probs_k64, cudaFuncAttributeMaxDynamicSharedMemorySize, smem_p);

    // 1) QKV projections, scatter to [B,H,S,Dh]
    const dim3 gp(HDIM / NB, (BDIM * SDIM) / MB, 1);
    gemm64<1><<<gp, 256, smem_g>>>(query,  Wq, bq, qbuf, HDIM, HDIM, 1.f);
    gemm64<1><<<gp, 256, smem_g>>>(key_in, Wk, bk, kbuf, HDIM, HDIM, 1.f);
    gemm64<1><<<gp, 256, smem_g>>>(value,  Wv, bv, vbuf, HDIM, HDIM, 1.f);

    // 2) Flash attention -> ctx + stats (no O(S^2) HBM traffic)
    flash_attn<<<dim3(SDIM / 128, BDIM * NH), 256, smem_f>>>(mask, cbuf, sbuf);

    // 3) Probs replay -> attention output (single 1.07 GB store pass)
    probs_k64<<<dim3(SDIM / 128, SDIM / 128, BDIM * NH), 256, smem_p>>>(
        qbuf, kbuf, att, mask, sbuf);

    // 4) Output projection -> x
    gemm64<0><<<gp, 256, smem_g>>>(cbuf, Wo, bo, out, HDIM, HDIM, 1.f);
}